// round 9
// baseline (speedup 1.0000x reference)
#include <cuda_runtime.h>
#include <cuda_fp16.h>
#include <math.h>
#include <cstdint>

#define NTOK 4096
#define DIM  512
#define HID  2048
#define NEXP 8
#define KTOT (NEXP * HID)
#define KSPLIT 8
#define KCHUNK (KTOT / KSPLIT)  // 2048

// ---------------------------------------------------------------------------
// Device scratch
// ---------------------------------------------------------------------------
__device__ __half g_xq[NTOK * DIM];
__device__ __half g_w1q[NEXP * DIM * HID];
__device__ __half g_w2q[KTOT * DIM];
__device__ __half g_Hq[(size_t)NTOK * KTOT];
__device__ float g_leaf[NTOK * NEXP];
__device__ float g_part[KSPLIT][NTOK * DIM];

// ---------------------------------------------------------------------------
// Tiling
// ---------------------------------------------------------------------------
#define BM 128
#define BN 128
#define BK 64
#define THREADS 256
#define STAGES 3
#define A_PITCH 72
#define B_PITCH 136
#define ASZB (BM * A_PITCH * 2)
#define BSZB (BK * B_PITCH * 2)
#define STAGEB (ASZB + BSZB)
#define SMEM_BYTES (STAGES * STAGEB)   // 107520

// ---------------------------------------------------------------------------
// PTX helpers
// ---------------------------------------------------------------------------
__device__ __forceinline__ uint32_t smem_u32(const void* p) {
    uint32_t a;
    asm("{ .reg .u64 t; cvta.to.shared.u64 t, %1; cvt.u32.u64 %0, t; }" : "=r"(a) : "l"(p));
    return a;
}
__device__ __forceinline__ void cp16(uint32_t dst, const void* src) {
    asm volatile("cp.async.cg.shared.global [%0], [%1], 16;" :: "r"(dst), "l"(src));
}
#define CP_COMMIT() asm volatile("cp.async.commit_group;" ::: "memory")
#define CP_WAIT1()  asm volatile("cp.async.wait_group 1;" ::: "memory")

__device__ __forceinline__ void ldsm_x4(uint32_t* r, uint32_t a) {
    asm volatile("ldmatrix.sync.aligned.m8n8.x4.shared.b16 {%0,%1,%2,%3}, [%4];"
                 : "=r"(r[0]), "=r"(r[1]), "=r"(r[2]), "=r"(r[3]) : "r"(a));
}
__device__ __forceinline__ void ldsm_x4t(uint32_t* r, uint32_t a) {
    asm volatile("ldmatrix.sync.aligned.m8n8.x4.trans.shared.b16 {%0,%1,%2,%3}, [%4];"
                 : "=r"(r[0]), "=r"(r[1]), "=r"(r[2]), "=r"(r[3]) : "r"(a));
}
__device__ __forceinline__ void mma16816(float* d, const uint32_t* a, const uint32_t* b) {
    asm volatile(
        "mma.sync.aligned.m16n8k16.row.col.f32.f16.f16.f32 "
        "{%0,%1,%2,%3},{%4,%5,%6,%7},{%8,%9},{%0,%1,%2,%3};"
        : "+f"(d[0]), "+f"(d[1]), "+f"(d[2]), "+f"(d[3])
        : "r"(a[0]), "r"(a[1]), "r"(a[2]), "r"(a[3]), "r"(b[0]), "r"(b[1]));
}
__device__ __forceinline__ float gelu_f(float h) {
    return 0.5f * h * (1.f + erff(h * 0.70710678118654752f));
}

// ---------------------------------------------------------------------------
// Multi-tile GEMM core, interleaved load issue (kk=0 compute first).
// Runs TILES consecutive B-tiles through ONE continuous pipeline; A shared.
// ---------------------------------------------------------------------------
template <int LDA, int LDB, int NK, int TILES, typename Epi>
__device__ __forceinline__ void gemm_multi(
    const __half* __restrict__ gA, const __half* __restrict__ gB,
    int bTileStride, uint32_t sb, Epi epi)
{
    const int tid = threadIdx.x;
    const int lane = tid & 31, wid = tid >> 5;
    const int wm = wid & 1, wn = wid >> 1;
    const int lr = lane & 15, lc = (lane >> 4) * 8;

    float c[16][4] = {};

    auto load_stage = [&](int s, int kt) {
        const int tIdx = kt / NK;
        const int k0 = (kt % NK) * BK;
        const __half* gBt = gB + (size_t)tIdx * bTileStride;
        uint32_t aB = sb + s * STAGEB;
        uint32_t bB = aB + ASZB;
#pragma unroll
        for (int i = 0; i < 4; i++) {
            int ch = tid + i * THREADS;
            int arow = ch >> 3, aseg = ch & 7;
            cp16(aB + (uint32_t)(arow * A_PITCH + aseg * 8) * 2,
                 gA + (size_t)arow * LDA + k0 + aseg * 8);
            int brow = ch >> 4, bseg = ch & 15;
            cp16(bB + (uint32_t)(brow * B_PITCH + bseg * 8) * 2,
                 gBt + (size_t)(k0 + brow) * LDB + bseg * 8);
        }
    };

    auto compute_kk = [&](uint32_t aB, uint32_t bB, int kk) {
        uint32_t a4[4][4], b4[4][2];
#pragma unroll
        for (int mi = 0; mi < 4; mi++) {
            uint32_t off = (uint32_t)((wm * 64 + mi * 16 + lr) * A_PITCH + kk * 16 + lc) * 2;
            ldsm_x4(a4[mi], aB + off);
        }
#pragma unroll
        for (int nj = 0; nj < 2; nj++) {
            uint32_t off = (uint32_t)((kk * 16 + lr) * B_PITCH + wn * 32 + nj * 16 + lc) * 2;
            uint32_t t4[4];
            ldsm_x4t(t4, bB + off);
            b4[nj * 2][0] = t4[0]; b4[nj * 2][1] = t4[1];
            b4[nj * 2 + 1][0] = t4[2]; b4[nj * 2 + 1][1] = t4[3];
        }
#pragma unroll
        for (int mi = 0; mi < 4; mi++)
#pragma unroll
            for (int ni = 0; ni < 4; ni++)
                mma16816(c[mi * 4 + ni], a4[mi], b4[ni]);
    };

    constexpr int NT = NK * TILES;
    load_stage(0, 0); CP_COMMIT();
    load_stage(1, 1); CP_COMMIT();

    for (int kt = 0; kt < NT; kt++) {
        CP_WAIT1();
        __syncthreads();

        const int s = kt % STAGES;
        uint32_t aB = sb + s * STAGEB;
        uint32_t bB = aB + ASZB;

        compute_kk(aB, bB, 0);               // HMMA flowing first

        if (kt + 2 < NT) load_stage((kt + 2) % STAGES, kt + 2);
        CP_COMMIT();

#pragma unroll
        for (int kk = 1; kk < BK / 16; kk++)
            compute_kk(aB, bB, kk);

        if ((kt % NK) == NK - 1) {
            epi(kt / NK, c);
#pragma unroll
            for (int q = 0; q < 16; q++)
#pragma unroll
                for (int j = 0; j < 4; j++) c[q][j] = 0.f;
        }
    }
}

// ---------------------------------------------------------------------------
// GEMM1: Hq[t, e*HID+h] = fp16( leaf[t,e] * gelu(x @ w1[e] + b1[e]) )
// grid (HID/256, NTOK/128, NEXP) = (8, 32, 8) = 2048 CTAs, 2 hb-tiles each
// ---------------------------------------------------------------------------
__global__ __launch_bounds__(THREADS, 2) void gemm1_kernel(const float* __restrict__ b1) {
    extern __shared__ char smem[];
    uint32_t sb = smem_u32(smem);
    const int e = blockIdx.z, nb = blockIdx.y * BM, hb0 = blockIdx.x * (2 * BN);

    const int tid = threadIdx.x, lane = tid & 31, wid = tid >> 5;
    const int wm = wid & 1, wn = wid >> 1;

    auto epi = [&](int tIdx, float (*c)[4]) {
        const int hb = hb0 + tIdx * BN;
#pragma unroll
        for (int mi = 0; mi < 4; mi++) {
            int r0 = wm * 64 + mi * 16 + (lane >> 2);
            int t0 = nb + r0, t1 = t0 + 8;
            float lw0 = g_leaf[t0 * NEXP + e];
            float lw1 = g_leaf[t1 * NEXP + e];
            size_t base0 = (size_t)t0 * KTOT + (size_t)e * HID + hb;
            size_t base1 = (size_t)t1 * KTOT + (size_t)e * HID + hb;
#pragma unroll
            for (int ni = 0; ni < 4; ni++) {
                int c0 = wn * 32 + ni * 8 + (lane & 3) * 2;
                float ba = b1[e * HID + hb + c0];
                float bb = b1[e * HID + hb + c0 + 1];
                const float* d = c[mi * 4 + ni];
                __half2 h0, h1;
                h0.x = __float2half_rn(lw0 * gelu_f(d[0] + ba));
                h0.y = __float2half_rn(lw0 * gelu_f(d[1] + bb));
                h1.x = __float2half_rn(lw1 * gelu_f(d[2] + ba));
                h1.y = __float2half_rn(lw1 * gelu_f(d[3] + bb));
                *(__half2*)(g_Hq + base0 + c0) = h0;
                *(__half2*)(g_Hq + base1 + c0) = h1;
            }
        }
    };

    gemm_multi<DIM, HID, DIM / BK, 2>(
        g_xq + (size_t)nb * DIM,
        g_w1q + (size_t)e * DIM * HID + hb0,
        BN, sb, epi);
}

// ---------------------------------------------------------------------------
// GEMM2 (split-K=8, single tile — R8 config): grid (4, 32, 8) = 1024 CTAs
// ---------------------------------------------------------------------------
__global__ __launch_bounds__(THREADS, 2) void gemm2_kernel() {
    extern __shared__ char smem[];
    uint32_t sb = smem_u32(smem);
    const int nb = blockIdx.y * BM, db = blockIdx.x * BN, z = blockIdx.z;

    const int tid = threadIdx.x, lane = tid & 31, wid = tid >> 5;
    const int wm = wid & 1, wn = wid >> 1;
    float* pz = g_part[z];

    auto epi = [&](int, float (*c)[4]) {
#pragma unroll
        for (int mi = 0; mi < 4; mi++) {
            int r0 = wm * 64 + mi * 16 + (lane >> 2);
            int t0 = nb + r0, t1 = t0 + 8;
#pragma unroll
            for (int ni = 0; ni < 4; ni++) {
                int c0 = wn * 32 + ni * 8 + (lane & 3) * 2;
                const float* d = c[mi * 4 + ni];
                *(float2*)(pz + (size_t)t0 * DIM + db + c0) = make_float2(d[0], d[1]);
                *(float2*)(pz + (size_t)t1 * DIM + db + c0) = make_float2(d[2], d[3]);
            }
        }
    };

    gemm_multi<KTOT, DIM, KCHUNK / BK, 1>(
        g_Hq + (size_t)nb * KTOT + (size_t)z * KCHUNK,
        g_w2q + (size_t)z * KCHUNK * DIM + db,
        0, sb, epi);
}

// ---------------------------------------------------------------------------
// Reduce: out = sum_z part[z] + sum_e leaf*b2
// ---------------------------------------------------------------------------
__global__ void reduce_kernel(const float* __restrict__ b2, float* __restrict__ out) {
    int i = blockIdx.x * blockDim.x + threadIdx.x;
    if (i >= NTOK * DIM / 4) return;
    int t = i >> 7;
    int dq = i & 127;

    float4 s = ((const float4*)g_part[0])[i];
#pragma unroll
    for (int z = 1; z < KSPLIT; z++) {
        float4 p = ((const float4*)g_part[z])[i];
        s.x += p.x; s.y += p.y; s.z += p.z; s.w += p.w;
    }
#pragma unroll
    for (int e = 0; e < NEXP; e++) {
        float lw = g_leaf[t * NEXP + e];
        float4 bv = ((const float4*)b2)[e * 128 + dq];
        s.x = fmaf(lw, bv.x, s.x);
        s.y = fmaf(lw, bv.y, s.y);
        s.z = fmaf(lw, bv.z, s.z);
        s.w = fmaf(lw, bv.w, s.w);
    }
    ((float4*)out)[i] = s;
}

// ---------------------------------------------------------------------------
// Merged converter
// ---------------------------------------------------------------------------
#define X4  (NTOK * DIM / 4)
#define W14 (NEXP * DIM * HID / 4)
#define W24 (KTOT * DIM / 4)

__global__ void conv_all_kernel(const float* __restrict__ x,
                                const float* __restrict__ w1,
                                const float* __restrict__ w2) {
    int i = blockIdx.x * blockDim.x + threadIdx.x;
    const float* src;
    __half* dst;
    int j;
    if (i < X4) { src = x; dst = g_xq; j = i; }
    else if (i < X4 + W14) { src = w1; dst = g_w1q; j = i - X4; }
    else if (i < X4 + W14 + W24) { src = w2; dst = g_w2q; j = i - X4 - W14; }
    else return;
    float4 v = ((const float4*)src)[j];
    __half h[4] = {__float2half_rn(v.x), __float2half_rn(v.y),
                   __float2half_rn(v.z), __float2half_rn(v.w)};
    *(uint2*)(dst + (size_t)j * 4) = *(uint2*)h;
}

// ---------------------------------------------------------------------------
// Router
// ---------------------------------------------------------------------------
__global__ void router_kernel(const float* __restrict__ x,
                              const float* __restrict__ rw,
                              const float* __restrict__ rb) {
    int gwarp = (blockIdx.x * blockDim.x + threadIdx.x) >> 5;
    int lane = threadIdx.x & 31;
    if (gwarp >= NTOK) return;
    const float* xr = x + (size_t)gwarp * DIM;
    float acc[7];
#pragma unroll
    for (int r = 0; r < 7; r++) acc[r] = 0.f;
    for (int k = lane; k < DIM; k += 32) {
        float xv = xr[k];
#pragma unroll
        for (int r = 0; r < 7; r++) acc[r] = fmaf(xv, rw[r * DIM + k], acc[r]);
    }
#pragma unroll
    for (int r = 0; r < 7; r++)
#pragma unroll
        for (int o = 16; o > 0; o >>= 1) acc[r] += __shfl_xor_sync(0xffffffffu, acc[r], o);
    if (lane < NEXP) {
        float p[7];
#pragma unroll
        for (int r = 0; r < 7; r++) p[r] = 1.f / (1.f + expf(-(acc[r] + rb[r])));
        int l = lane;
        int b0 = (l >> 2) & 1, b1i = (l >> 1) & 1, b2i = l & 1;
        float f0 = b0 ? p[0] : (1.f - p[0]);
        float q1 = b0 ? p[2] : p[1];
        float f1 = b1i ? q1 : (1.f - q1);
        int i2 = l >> 1;
        float q2 = (i2 == 0) ? p[3] : (i2 == 1) ? p[4] : (i2 == 2) ? p[5] : p[6];
        float f2 = b2i ? q2 : (1.f - q2);
        g_leaf[gwarp * NEXP + l] = f0 * f1 * f2;
    }
}

// ---------------------------------------------------------------------------
extern "C" void kernel_launch(void* const* d_in, const int* in_sizes, int n_in,
                              void* d_out, int out_size) {
    const float* x  = (const float*)d_in[0];
    const float* rw = (const float*)d_in[1];
    const float* rb = (const float*)d_in[2];
    const float* w1 = (const float*)d_in[3];
    const float* b1 = (const float*)d_in[4];
    const float* w2 = (const float*)d_in[5];
    const float* b2 = (const float*)d_in[6];
    float* out = (float*)d_out;

    cudaFuncSetAttribute(gemm1_kernel, cudaFuncAttributeMaxDynamicSharedMemorySize, SMEM_BYTES);
    cudaFuncSetAttribute(gemm2_kernel, cudaFuncAttributeMaxDynamicSharedMemorySize, SMEM_BYTES);

    conv_all_kernel<<<(X4 + W14 + W24 + 255) / 256, 256>>>(x, w1, w2);
    router_kernel<<<NTOK / 8, 256>>>(x, rw, rb);

    gemm1_kernel<<<dim3(HID / (2 * BN), NTOK / BM, NEXP), THREADS, SMEM_BYTES>>>(b1);
    gemm2_kernel<<<dim3(DIM / BN, NTOK / BM, KSPLIT), THREADS, SMEM_BYTES>>>();
    reduce_kernel<<<(NTOK * DIM / 4 + 255) / 256, 256>>>(b2, out);
}

// round 10
// speedup vs baseline: 1.0615x; 1.0615x over previous
#include <cuda_runtime.h>
#include <cuda_fp16.h>
#include <math.h>
#include <cstdint>

#define NTOK 4096
#define DIM  512
#define HID  2048
#define NEXP 8
#define KTOT (NEXP * HID)
#define KSPLIT 8
#define KCHUNK (KTOT / KSPLIT)  // 2048

// ---------------------------------------------------------------------------
// Device scratch
// ---------------------------------------------------------------------------
__device__ __half g_xq[NTOK * DIM];
__device__ __half g_w1q[NEXP * DIM * HID];
__device__ __half g_w2q[KTOT * DIM];
__device__ __half g_Hq[(size_t)NTOK * KTOT];
__device__ float g_leaf[NTOK * NEXP];
__device__ float g_part[KSPLIT][NTOK * DIM];

// ---------------------------------------------------------------------------
// Tiling
// ---------------------------------------------------------------------------
#define BM 128
#define BN 128
#define BK 64
#define THREADS 256
#define STAGES 3
#define A_PITCH 72
#define B_PITCH 136
#define ASZB (BM * A_PITCH * 2)
#define BSZB (BK * B_PITCH * 2)
#define STAGEB (ASZB + BSZB)
#define SMEM_BYTES (STAGES * STAGEB)   // 107520

// ---------------------------------------------------------------------------
// PTX helpers
// ---------------------------------------------------------------------------
__device__ __forceinline__ uint32_t smem_u32(const void* p) {
    uint32_t a;
    asm("{ .reg .u64 t; cvta.to.shared.u64 t, %1; cvt.u32.u64 %0, t; }" : "=r"(a) : "l"(p));
    return a;
}
__device__ __forceinline__ void cp16(uint32_t dst, const void* src) {
    asm volatile("cp.async.cg.shared.global [%0], [%1], 16;" :: "r"(dst), "l"(src));
}
#define CP_COMMIT() asm volatile("cp.async.commit_group;" ::: "memory")
#define CP_WAIT1()  asm volatile("cp.async.wait_group 1;" ::: "memory")

__device__ __forceinline__ void ldsm_x4(uint32_t* r, uint32_t a) {
    asm volatile("ldmatrix.sync.aligned.m8n8.x4.shared.b16 {%0,%1,%2,%3}, [%4];"
                 : "=r"(r[0]), "=r"(r[1]), "=r"(r[2]), "=r"(r[3]) : "r"(a));
}
__device__ __forceinline__ void ldsm_x4t(uint32_t* r, uint32_t a) {
    asm volatile("ldmatrix.sync.aligned.m8n8.x4.trans.shared.b16 {%0,%1,%2,%3}, [%4];"
                 : "=r"(r[0]), "=r"(r[1]), "=r"(r[2]), "=r"(r[3]) : "r"(a));
}
__device__ __forceinline__ void mma16816(float* d, const uint32_t* a, const uint32_t* b) {
    asm volatile(
        "mma.sync.aligned.m16n8k16.row.col.f32.f16.f16.f32 "
        "{%0,%1,%2,%3},{%4,%5,%6,%7},{%8,%9},{%0,%1,%2,%3};"
        : "+f"(d[0]), "+f"(d[1]), "+f"(d[2]), "+f"(d[3])
        : "r"(a[0]), "r"(a[1]), "r"(a[2]), "r"(a[3]), "r"(b[0]), "r"(b[1]));
}
__device__ __forceinline__ float gelu_f(float h) {
    return 0.5f * h * (1.f + erff(h * 0.70710678118654752f));
}

// ---------------------------------------------------------------------------
// GEMM core: interleaved, with the cp.async burst split across kk=0 and kk=1.
// ---------------------------------------------------------------------------
template <int LDA, int LDB, int NK>
__device__ __forceinline__ void gemm_core(
    const __half* __restrict__ gA, const __half* __restrict__ gB,
    uint32_t sb, float (*c)[4])
{
    const int tid = threadIdx.x;
    const int lane = tid & 31, wid = tid >> 5;
    const int wm = wid & 1, wn = wid >> 1;
    const int lr = lane & 15, lc = (lane >> 4) * 8;

    // half = 0 -> chunks 0..1, half = 1 -> chunks 2..3 (of 4)
    auto load_half = [&](int s, int kt, int half) {
        const int k0 = kt * BK;
        uint32_t aB = sb + s * STAGEB;
        uint32_t bB = aB + ASZB;
#pragma unroll
        for (int i = half * 2; i < half * 2 + 2; i++) {
            int ch = tid + i * THREADS;
            int arow = ch >> 3, aseg = ch & 7;
            cp16(aB + (uint32_t)(arow * A_PITCH + aseg * 8) * 2,
                 gA + (size_t)arow * LDA + k0 + aseg * 8);
            int brow = ch >> 4, bseg = ch & 15;
            cp16(bB + (uint32_t)(brow * B_PITCH + bseg * 8) * 2,
                 gB + (size_t)(k0 + brow) * LDB + bseg * 8);
        }
    };

    auto compute_kk = [&](uint32_t aB, uint32_t bB, int kk) {
        uint32_t a4[4][4], b4[4][2];
#pragma unroll
        for (int mi = 0; mi < 4; mi++) {
            uint32_t off = (uint32_t)((wm * 64 + mi * 16 + lr) * A_PITCH + kk * 16 + lc) * 2;
            ldsm_x4(a4[mi], aB + off);
        }
#pragma unroll
        for (int nj = 0; nj < 2; nj++) {
            uint32_t off = (uint32_t)((kk * 16 + lr) * B_PITCH + wn * 32 + nj * 16 + lc) * 2;
            uint32_t t4[4];
            ldsm_x4t(t4, bB + off);
            b4[nj * 2][0] = t4[0]; b4[nj * 2][1] = t4[1];
            b4[nj * 2 + 1][0] = t4[2]; b4[nj * 2 + 1][1] = t4[3];
        }
#pragma unroll
        for (int mi = 0; mi < 4; mi++)
#pragma unroll
            for (int ni = 0; ni < 4; ni++)
                mma16816(c[mi * 4 + ni], a4[mi], b4[ni]);
    };

    load_half(0, 0, 0); load_half(0, 0, 1); CP_COMMIT();
    load_half(1, 1, 0); load_half(1, 1, 1); CP_COMMIT();

    for (int kt = 0; kt < NK; kt++) {
        CP_WAIT1();
        __syncthreads();

        const int s = kt % STAGES;
        const int sn = (kt + 2) % STAGES;
        const bool more = (kt + 2 < NK);
        uint32_t aB = sb + s * STAGEB;
        uint32_t bB = aB + ASZB;

        compute_kk(aB, bB, 0);               // HMMA flowing first
        if (more) load_half(sn, kt + 2, 0);  // half the burst

        compute_kk(aB, bB, 1);
        if (more) load_half(sn, kt + 2, 1);  // other half
        CP_COMMIT();

        compute_kk(aB, bB, 2);
        compute_kk(aB, bB, 3);
    }
}

// ---------------------------------------------------------------------------
// GEMM1: Hq[t, e*HID+h] = fp16( leaf[t,e] * gelu(x @ w1[e] + b1[e]) )
// grid (HID/128, NTOK/128, NEXP) = 4096 CTAs
// ---------------------------------------------------------------------------
__global__ __launch_bounds__(THREADS, 2) void gemm1_kernel(const float* __restrict__ b1) {
    extern __shared__ char smem[];
    uint32_t sb = smem_u32(smem);
    const int e = blockIdx.z, nb = blockIdx.y * BM, hb = blockIdx.x * BN;

    float c[16][4] = {};
    gemm_core<DIM, HID, DIM / BK>(
        g_xq + (size_t)nb * DIM, g_w1q + (size_t)e * DIM * HID + hb, sb, c);

    const int tid = threadIdx.x, lane = tid & 31, wid = tid >> 5;
    const int wm = wid & 1, wn = wid >> 1;

#pragma unroll
    for (int mi = 0; mi < 4; mi++) {
        int r0 = wm * 64 + mi * 16 + (lane >> 2);
        int t0 = nb + r0, t1 = t0 + 8;
        float lw0 = g_leaf[t0 * NEXP + e];
        float lw1 = g_leaf[t1 * NEXP + e];
        size_t base0 = (size_t)t0 * KTOT + (size_t)e * HID + hb;
        size_t base1 = (size_t)t1 * KTOT + (size_t)e * HID + hb;
#pragma unroll
        for (int ni = 0; ni < 4; ni++) {
            int c0 = wn * 32 + ni * 8 + (lane & 3) * 2;
            float ba = b1[e * HID + hb + c0];
            float bb = b1[e * HID + hb + c0 + 1];
            const float* d = c[mi * 4 + ni];
            __half2 h0, h1;
            h0.x = __float2half_rn(lw0 * gelu_f(d[0] + ba));
            h0.y = __float2half_rn(lw0 * gelu_f(d[1] + bb));
            h1.x = __float2half_rn(lw1 * gelu_f(d[2] + ba));
            h1.y = __float2half_rn(lw1 * gelu_f(d[3] + bb));
            *(__half2*)(g_Hq + base0 + c0) = h0;
            *(__half2*)(g_Hq + base1 + c0) = h1;
        }
    }
}

// ---------------------------------------------------------------------------
// GEMM2 (split-K=8): grid (DIM/128, NTOK/128, KSPLIT) = 1024 CTAs
// ---------------------------------------------------------------------------
__global__ __launch_bounds__(THREADS, 2) void gemm2_kernel() {
    extern __shared__ char smem[];
    uint32_t sb = smem_u32(smem);
    const int nb = blockIdx.y * BM, db = blockIdx.x * BN, z = blockIdx.z;

    float c[16][4] = {};
    gemm_core<KTOT, DIM, KCHUNK / BK>(
        g_Hq + (size_t)nb * KTOT + (size_t)z * KCHUNK,
        g_w2q + (size_t)z * KCHUNK * DIM + db, sb, c);

    const int tid = threadIdx.x, lane = tid & 31, wid = tid >> 5;
    const int wm = wid & 1, wn = wid >> 1;
    float* pz = g_part[z];

#pragma unroll
    for (int mi = 0; mi < 4; mi++) {
        int r0 = wm * 64 + mi * 16 + (lane >> 2);
        int t0 = nb + r0, t1 = t0 + 8;
#pragma unroll
        for (int ni = 0; ni < 4; ni++) {
            int c0 = wn * 32 + ni * 8 + (lane & 3) * 2;
            const float* d = c[mi * 4 + ni];
            *(float2*)(pz + (size_t)t0 * DIM + db + c0) = make_float2(d[0], d[1]);
            *(float2*)(pz + (size_t)t1 * DIM + db + c0) = make_float2(d[2], d[3]);
        }
    }
}

// ---------------------------------------------------------------------------
// Reduce: out = sum_z part[z] + sum_e leaf*b2
// ---------------------------------------------------------------------------
__global__ void reduce_kernel(const float* __restrict__ b2, float* __restrict__ out) {
    int i = blockIdx.x * blockDim.x + threadIdx.x;
    if (i >= NTOK * DIM / 4) return;
    int t = i >> 7;
    int dq = i & 127;

    float4 s = ((const float4*)g_part[0])[i];
#pragma unroll
    for (int z = 1; z < KSPLIT; z++) {
        float4 p = ((const float4*)g_part[z])[i];
        s.x += p.x; s.y += p.y; s.z += p.z; s.w += p.w;
    }
#pragma unroll
    for (int e = 0; e < NEXP; e++) {
        float lw = g_leaf[t * NEXP + e];
        float4 bv = ((const float4*)b2)[e * 128 + dq];
        s.x = fmaf(lw, bv.x, s.x);
        s.y = fmaf(lw, bv.y, s.y);
        s.z = fmaf(lw, bv.z, s.z);
        s.w = fmaf(lw, bv.w, s.w);
    }
    ((float4*)out)[i] = s;
}

// ---------------------------------------------------------------------------
// Merged converter
// ---------------------------------------------------------------------------
#define X4  (NTOK * DIM / 4)
#define W14 (NEXP * DIM * HID / 4)
#define W24 (KTOT * DIM / 4)

__global__ void conv_all_kernel(const float* __restrict__ x,
                                const float* __restrict__ w1,
                                const float* __restrict__ w2) {
    int i = blockIdx.x * blockDim.x + threadIdx.x;
    const float* src;
    __half* dst;
    int j;
    if (i < X4) { src = x; dst = g_xq; j = i; }
    else if (i < X4 + W14) { src = w1; dst = g_w1q; j = i - X4; }
    else if (i < X4 + W14 + W24) { src = w2; dst = g_w2q; j = i - X4 - W14; }
    else return;
    float4 v = ((const float4*)src)[j];
    __half h[4] = {__float2half_rn(v.x), __float2half_rn(v.y),
                   __float2half_rn(v.z), __float2half_rn(v.w)};
    *(uint2*)(dst + (size_t)j * 4) = *(uint2*)h;
}

// ---------------------------------------------------------------------------
// Router
// ---------------------------------------------------------------------------
__global__ void router_kernel(const float* __restrict__ x,
                              const float* __restrict__ rw,
                              const float* __restrict__ rb) {
    int gwarp = (blockIdx.x * blockDim.x + threadIdx.x) >> 5;
    int lane = threadIdx.x & 31;
    if (gwarp >= NTOK) return;
    const float* xr = x + (size_t)gwarp * DIM;
    float acc[7];
#pragma unroll
    for (int r = 0; r < 7; r++) acc[r] = 0.f;
    for (int k = lane; k < DIM; k += 32) {
        float xv = xr[k];
#pragma unroll
        for (int r = 0; r < 7; r++) acc[r] = fmaf(xv, rw[r * DIM + k], acc[r]);
    }
#pragma unroll
    for (int r = 0; r < 7; r++)
#pragma unroll
        for (int o = 16; o > 0; o >>= 1) acc[r] += __shfl_xor_sync(0xffffffffu, acc[r], o);
    if (lane < NEXP) {
        float p[7];
#pragma unroll
        for (int r = 0; r < 7; r++) p[r] = 1.f / (1.f + expf(-(acc[r] + rb[r])));
        int l = lane;
        int b0 = (l >> 2) & 1, b1i = (l >> 1) & 1, b2i = l & 1;
        float f0 = b0 ? p[0] : (1.f - p[0]);
        float q1 = b0 ? p[2] : p[1];
        float f1 = b1i ? q1 : (1.f - q1);
        int i2 = l >> 1;
        float q2 = (i2 == 0) ? p[3] : (i2 == 1) ? p[4] : (i2 == 2) ? p[5] : p[6];
        float f2 = b2i ? q2 : (1.f - q2);
        g_leaf[gwarp * NEXP + l] = f0 * f1 * f2;
    }
}

// ---------------------------------------------------------------------------
extern "C" void kernel_launch(void* const* d_in, const int* in_sizes, int n_in,
                              void* d_out, int out_size) {
    const float* x  = (const float*)d_in[0];
    const float* rw = (const float*)d_in[1];
    const float* rb = (const float*)d_in[2];
    const float* w1 = (const float*)d_in[3];
    const float* b1 = (const float*)d_in[4];
    const float* w2 = (const float*)d_in[5];
    const float* b2 = (const float*)d_in[6];
    float* out = (float*)d_out;

    cudaFuncSetAttribute(gemm1_kernel, cudaFuncAttributeMaxDynamicSharedMemorySize, SMEM_BYTES);
    cudaFuncSetAttribute(gemm2_kernel, cudaFuncAttributeMaxDynamicSharedMemorySize, SMEM_BYTES);

    conv_all_kernel<<<(X4 + W14 + W24 + 255) / 256, 256>>>(x, w1, w2);
    router_kernel<<<NTOK / 8, 256>>>(x, rw, rb);

    gemm1_kernel<<<dim3(HID / BN, NTOK / BM, NEXP), THREADS, SMEM_BYTES>>>(b1);
    gemm2_kernel<<<dim3(DIM / BN, NTOK / BM, KSPLIT), THREADS, SMEM_BYTES>>>();
    reduce_kernel<<<(NTOK * DIM / 4 + 255) / 256, 256>>>(b2, out);
}

// round 11
// speedup vs baseline: 1.1187x; 1.0538x over previous
#include <cuda_runtime.h>
#include <cuda_fp16.h>
#include <math.h>
#include <cstdint>

#define NTOK 4096
#define DIM  512
#define HID  2048
#define NEXP 8
#define KTOT (NEXP * HID)
#define KSPLIT 8
#define KCHUNK (KTOT / KSPLIT)  // 2048

// ---------------------------------------------------------------------------
// Device scratch
// ---------------------------------------------------------------------------
__device__ __half g_xq[NTOK * DIM];
__device__ __half g_w1q[NEXP * DIM * HID];
__device__ __half g_w2q[KTOT * DIM];
__device__ __half g_Hq[(size_t)NTOK * KTOT];
__device__ float g_leaf[NTOK * NEXP];
__device__ float g_part[KSPLIT][NTOK * DIM];

// ---------------------------------------------------------------------------
// Tiling
// ---------------------------------------------------------------------------
#define BM 128
#define BN 128
#define BK 64
#define THREADS 256
#define STAGES 3
#define A_PITCH 72
#define B_PITCH 136
#define ASZB (BM * A_PITCH * 2)
#define BSZB (BK * B_PITCH * 2)
#define STAGEB (ASZB + BSZB)
#define SMEM_BYTES (STAGES * STAGEB)   // 107520

// ---------------------------------------------------------------------------
// PTX helpers
// ---------------------------------------------------------------------------
__device__ __forceinline__ uint32_t smem_u32(const void* p) {
    uint32_t a;
    asm("{ .reg .u64 t; cvta.to.shared.u64 t, %1; cvt.u32.u64 %0, t; }" : "=r"(a) : "l"(p));
    return a;
}
__device__ __forceinline__ void cp16(uint32_t dst, const void* src) {
    asm volatile("cp.async.cg.shared.global [%0], [%1], 16;" :: "r"(dst), "l"(src));
}
#define CP_COMMIT() asm volatile("cp.async.commit_group;" ::: "memory")
#define CP_WAIT1()  asm volatile("cp.async.wait_group 1;" ::: "memory")

__device__ __forceinline__ void ldsm_x4(uint32_t* r, uint32_t a) {
    asm volatile("ldmatrix.sync.aligned.m8n8.x4.shared.b16 {%0,%1,%2,%3}, [%4];"
                 : "=r"(r[0]), "=r"(r[1]), "=r"(r[2]), "=r"(r[3]) : "r"(a));
}
__device__ __forceinline__ void ldsm_x4t(uint32_t* r, uint32_t a) {
    asm volatile("ldmatrix.sync.aligned.m8n8.x4.trans.shared.b16 {%0,%1,%2,%3}, [%4];"
                 : "=r"(r[0]), "=r"(r[1]), "=r"(r[2]), "=r"(r[3]) : "r"(a));
}
__device__ __forceinline__ void mma16816(float* d, const uint32_t* a, const uint32_t* b) {
    asm volatile(
        "mma.sync.aligned.m16n8k16.row.col.f32.f16.f16.f32 "
        "{%0,%1,%2,%3},{%4,%5,%6,%7},{%8,%9},{%0,%1,%2,%3};"
        : "+f"(d[0]), "+f"(d[1]), "+f"(d[2]), "+f"(d[3])
        : "r"(a[0]), "r"(a[1]), "r"(a[2]), "r"(a[3]), "r"(b[0]), "r"(b[1]));
}
__device__ __forceinline__ float gelu_f(float h) {
    return 0.5f * h * (1.f + erff(h * 0.70710678118654752f));
}

// ---------------------------------------------------------------------------
// GEMM core: cp.async burst quarter-split across the 4 kk sub-steps.
// ---------------------------------------------------------------------------
template <int LDA, int LDB, int NK>
__device__ __forceinline__ void gemm_core(
    const __half* __restrict__ gA, const __half* __restrict__ gB,
    uint32_t sb, float (*c)[4])
{
    const int tid = threadIdx.x;
    const int lane = tid & 31, wid = tid >> 5;
    const int wm = wid & 1, wn = wid >> 1;
    const int lr = lane & 15, lc = (lane >> 4) * 8;

    // quarter q in 0..3: one (A, B) cp16 pair per thread
    auto load_q = [&](int s, int kt, int q) {
        const int k0 = kt * BK;
        uint32_t aB = sb + s * STAGEB;
        uint32_t bB = aB + ASZB;
        int ch = tid + q * THREADS;
        int arow = ch >> 3, aseg = ch & 7;
        cp16(aB + (uint32_t)(arow * A_PITCH + aseg * 8) * 2,
             gA + (size_t)arow * LDA + k0 + aseg * 8);
        int brow = ch >> 4, bseg = ch & 15;
        cp16(bB + (uint32_t)(brow * B_PITCH + bseg * 8) * 2,
             gB + (size_t)(k0 + brow) * LDB + bseg * 8);
    };

    auto compute_kk = [&](uint32_t aB, uint32_t bB, int kk) {
        uint32_t a4[4][4], b4[4][2];
#pragma unroll
        for (int mi = 0; mi < 4; mi++) {
            uint32_t off = (uint32_t)((wm * 64 + mi * 16 + lr) * A_PITCH + kk * 16 + lc) * 2;
            ldsm_x4(a4[mi], aB + off);
        }
#pragma unroll
        for (int nj = 0; nj < 2; nj++) {
            uint32_t off = (uint32_t)((kk * 16 + lr) * B_PITCH + wn * 32 + nj * 16 + lc) * 2;
            uint32_t t4[4];
            ldsm_x4t(t4, bB + off);
            b4[nj * 2][0] = t4[0]; b4[nj * 2][1] = t4[1];
            b4[nj * 2 + 1][0] = t4[2]; b4[nj * 2 + 1][1] = t4[3];
        }
#pragma unroll
        for (int mi = 0; mi < 4; mi++)
#pragma unroll
            for (int ni = 0; ni < 4; ni++)
                mma16816(c[mi * 4 + ni], a4[mi], b4[ni]);
    };

#pragma unroll
    for (int q = 0; q < 4; q++) load_q(0, 0, q);
    CP_COMMIT();
#pragma unroll
    for (int q = 0; q < 4; q++) load_q(1, 1, q);
    CP_COMMIT();

    for (int kt = 0; kt < NK; kt++) {
        CP_WAIT1();
        __syncthreads();

        const int s = kt % STAGES;
        const int sn = (kt + 2) % STAGES;
        const bool more = (kt + 2 < NK);
        uint32_t aB = sb + s * STAGEB;
        uint32_t bB = aB + ASZB;

#pragma unroll
        for (int kk = 0; kk < 4; kk++) {
            compute_kk(aB, bB, kk);
            if (more) load_q(sn, kt + 2, kk);
        }
        CP_COMMIT();
    }
}

// ---------------------------------------------------------------------------
// GEMM1: Hq[t, e*HID+h] = fp16( leaf[t,e] * gelu(x @ w1[e] + b1[e]) )
// grid (HID/128, NTOK/128, NEXP) = 4096 CTAs
// ---------------------------------------------------------------------------
__global__ __launch_bounds__(THREADS, 2) void gemm1_kernel(const float* __restrict__ b1) {
    extern __shared__ char smem[];
    uint32_t sb = smem_u32(smem);
    const int e = blockIdx.z, nb = blockIdx.y * BM, hb = blockIdx.x * BN;

    float c[16][4] = {};
    gemm_core<DIM, HID, DIM / BK>(
        g_xq + (size_t)nb * DIM, g_w1q + (size_t)e * DIM * HID + hb, sb, c);

    const int tid = threadIdx.x, lane = tid & 31, wid = tid >> 5;
    const int wm = wid & 1, wn = wid >> 1;

#pragma unroll
    for (int mi = 0; mi < 4; mi++) {
        int r0 = wm * 64 + mi * 16 + (lane >> 2);
        int t0 = nb + r0, t1 = t0 + 8;
        float lw0 = g_leaf[t0 * NEXP + e];
        float lw1 = g_leaf[t1 * NEXP + e];
        size_t base0 = (size_t)t0 * KTOT + (size_t)e * HID + hb;
        size_t base1 = (size_t)t1 * KTOT + (size_t)e * HID + hb;
#pragma unroll
        for (int ni = 0; ni < 4; ni++) {
            int c0 = wn * 32 + ni * 8 + (lane & 3) * 2;
            float ba = b1[e * HID + hb + c0];
            float bb = b1[e * HID + hb + c0 + 1];
            const float* d = c[mi * 4 + ni];
            __half2 h0, h1;
            h0.x = __float2half_rn(lw0 * gelu_f(d[0] + ba));
            h0.y = __float2half_rn(lw0 * gelu_f(d[1] + bb));
            h1.x = __float2half_rn(lw1 * gelu_f(d[2] + ba));
            h1.y = __float2half_rn(lw1 * gelu_f(d[3] + bb));
            *(__half2*)(g_Hq + base0 + c0) = h0;
            *(__half2*)(g_Hq + base1 + c0) = h1;
        }
    }
}

// ---------------------------------------------------------------------------
// GEMM2 (split-K=8): grid (DIM/128, NTOK/128, KSPLIT) = 1024 CTAs
// ---------------------------------------------------------------------------
__global__ __launch_bounds__(THREADS, 2) void gemm2_kernel() {
    extern __shared__ char smem[];
    uint32_t sb = smem_u32(smem);
    const int nb = blockIdx.y * BM, db = blockIdx.x * BN, z = blockIdx.z;

    float c[16][4] = {};
    gemm_core<KTOT, DIM, KCHUNK / BK>(
        g_Hq + (size_t)nb * KTOT + (size_t)z * KCHUNK,
        g_w2q + (size_t)z * KCHUNK * DIM + db, sb, c);

    const int tid = threadIdx.x, lane = tid & 31, wid = tid >> 5;
    const int wm = wid & 1, wn = wid >> 1;
    float* pz = g_part[z];

#pragma unroll
    for (int mi = 0; mi < 4; mi++) {
        int r0 = wm * 64 + mi * 16 + (lane >> 2);
        int t0 = nb + r0, t1 = t0 + 8;
#pragma unroll
        for (int ni = 0; ni < 4; ni++) {
            int c0 = wn * 32 + ni * 8 + (lane & 3) * 2;
            const float* d = c[mi * 4 + ni];
            *(float2*)(pz + (size_t)t0 * DIM + db + c0) = make_float2(d[0], d[1]);
            *(float2*)(pz + (size_t)t1 * DIM + db + c0) = make_float2(d[2], d[3]);
        }
    }
}

// ---------------------------------------------------------------------------
// Reduce: out = sum_z part[z] + sum_e leaf*b2
// ---------------------------------------------------------------------------
__global__ void reduce_kernel(const float* __restrict__ b2, float* __restrict__ out) {
    int i = blockIdx.x * blockDim.x + threadIdx.x;
    if (i >= NTOK * DIM / 4) return;
    int t = i >> 7;
    int dq = i & 127;

    float4 s = ((const float4*)g_part[0])[i];
#pragma unroll
    for (int z = 1; z < KSPLIT; z++) {
        float4 p = ((const float4*)g_part[z])[i];
        s.x += p.x; s.y += p.y; s.z += p.z; s.w += p.w;
    }
#pragma unroll
    for (int e = 0; e < NEXP; e++) {
        float lw = g_leaf[t * NEXP + e];
        float4 bv = ((const float4*)b2)[e * 128 + dq];
        s.x = fmaf(lw, bv.x, s.x);
        s.y = fmaf(lw, bv.y, s.y);
        s.z = fmaf(lw, bv.z, s.z);
        s.w = fmaf(lw, bv.w, s.w);
    }
    ((float4*)out)[i] = s;
}

// ---------------------------------------------------------------------------
// Merged converter
// ---------------------------------------------------------------------------
#define X4  (NTOK * DIM / 4)
#define W14 (NEXP * DIM * HID / 4)
#define W24 (KTOT * DIM / 4)

__global__ void conv_all_kernel(const float* __restrict__ x,
                                const float* __restrict__ w1,
                                const float* __restrict__ w2) {
    int i = blockIdx.x * blockDim.x + threadIdx.x;
    const float* src;
    __half* dst;
    int j;
    if (i < X4) { src = x; dst = g_xq; j = i; }
    else if (i < X4 + W14) { src = w1; dst = g_w1q; j = i - X4; }
    else if (i < X4 + W14 + W24) { src = w2; dst = g_w2q; j = i - X4 - W14; }
    else return;
    float4 v = ((const float4*)src)[j];
    __half h[4] = {__float2half_rn(v.x), __float2half_rn(v.y),
                   __float2half_rn(v.z), __float2half_rn(v.w)};
    *(uint2*)(dst + (size_t)j * 4) = *(uint2*)h;
}

// ---------------------------------------------------------------------------
// Router — float4 loads, MLP 4
// ---------------------------------------------------------------------------
__global__ void router_kernel(const float* __restrict__ x,
                              const float* __restrict__ rw,
                              const float* __restrict__ rb) {
    int gwarp = (blockIdx.x * blockDim.x + threadIdx.x) >> 5;
    int lane = threadIdx.x & 31;
    if (gwarp >= NTOK) return;
    const float4* xr4 = (const float4*)(x + (size_t)gwarp * DIM);
    const float4* rw4 = (const float4*)rw;

    float acc[7];
#pragma unroll
    for (int r = 0; r < 7; r++) acc[r] = 0.f;

#pragma unroll
    for (int q = 0; q < 4; q++) {
        int idx = lane + q * 32;              // float4 index within row (0..127)
        float4 xv = xr4[idx];
#pragma unroll
        for (int r = 0; r < 7; r++) {
            float4 wv = rw4[r * 128 + idx];
            acc[r] = fmaf(xv.x, wv.x, acc[r]);
            acc[r] = fmaf(xv.y, wv.y, acc[r]);
            acc[r] = fmaf(xv.z, wv.z, acc[r]);
            acc[r] = fmaf(xv.w, wv.w, acc[r]);
        }
    }
#pragma unroll
    for (int r = 0; r < 7; r++)
#pragma unroll
        for (int o = 16; o > 0; o >>= 1) acc[r] += __shfl_xor_sync(0xffffffffu, acc[r], o);
    if (lane < NEXP) {
        float p[7];
#pragma unroll
        for (int r = 0; r < 7; r++) p[r] = 1.f / (1.f + expf(-(acc[r] + rb[r])));
        int l = lane;
        int b0 = (l >> 2) & 1, b1i = (l >> 1) & 1, b2i = l & 1;
        float f0 = b0 ? p[0] : (1.f - p[0]);
        float q1 = b0 ? p[2] : p[1];
        float f1 = b1i ? q1 : (1.f - q1);
        int i2 = l >> 1;
        float q2 = (i2 == 0) ? p[3] : (i2 == 1) ? p[4] : (i2 == 2) ? p[5] : p[6];
        float f2 = b2i ? q2 : (1.f - q2);
        g_leaf[gwarp * NEXP + l] = f0 * f1 * f2;
    }
}

// ---------------------------------------------------------------------------
extern "C" void kernel_launch(void* const* d_in, const int* in_sizes, int n_in,
                              void* d_out, int out_size) {
    const float* x  = (const float*)d_in[0];
    const float* rw = (const float*)d_in[1];
    const float* rb = (const float*)d_in[2];
    const float* w1 = (const float*)d_in[3];
    const float* b1 = (const float*)d_in[4];
    const float* w2 = (const float*)d_in[5];
    const float* b2 = (const float*)d_in[6];
    float* out = (float*)d_out;

    cudaFuncSetAttribute(gemm1_kernel, cudaFuncAttributeMaxDynamicSharedMemorySize, SMEM_BYTES);
    cudaFuncSetAttribute(gemm2_kernel, cudaFuncAttributeMaxDynamicSharedMemorySize, SMEM_BYTES);

    conv_all_kernel<<<(X4 + W14 + W24 + 255) / 256, 256>>>(x, w1, w2);
    router_kernel<<<NTOK / 8, 256>>>(x, rw, rb);

    gemm1_kernel<<<dim3(HID / BN, NTOK / BM, NEXP), THREADS, SMEM_BYTES>>>(b1);
    gemm2_kernel<<<dim3(DIM / BN, NTOK / BM, KSPLIT), THREADS, SMEM_BYTES>>>();
    reduce_kernel<<<(NTOK * DIM / 4 + 255) / 256, 256>>>(b2, out);
}